// round 16
// baseline (speedup 1.0000x reference)
#include <cuda_runtime.h>
#include <cstdint>

#define NCC   80
#define NGMAX 300
#define NPMAX 100000
#define EPSF  1e-7f
#define C_V   0.4052847345693511f   // 4/pi^2
#define NB    444                   // 3 blocks/SM on 148 SMs (co-resident on 152 too)
#define NT    512                   // 16 warps/block -> 48 warps/SM
#define GCH   16                    // sorted g-rows per cost unit

// ---- scratch (static device arrays; 16B-aligned for vector access) ----
__device__ __align__(16) float d_probT[(size_t)NCC * NPMAX];   // [class][pred]
__device__ __align__(16) float d_px1[NPMAX], d_py1[NPMAX], d_px2[NPMAX], d_py2[NPMAX];
__device__ __align__(16) float d_parea[NPMAX], d_patan[NPMAX], d_pcx[NPMAX], d_pcy[NPMAX];
__device__ float d_gx1[NGMAX], d_gy1[NGMAX], d_gx2[NGMAX], d_gy2[NGMAX];
__device__ float d_garea[NGMAX], d_gatan[NGMAX], d_gcx[NGMAX], d_gcy[NGMAX];
__device__ int   d_gcls[NGMAX];
__device__ int   d_sorder[NGMAX];   // gt indices sorted by class

// barrier + work counters
__device__ unsigned d_bar_count = 0;
__device__ unsigned d_bar_gen   = 0;
__device__ unsigned d_unit_ctr  = 0;
__device__ unsigned d_row_ctr   = 0;

__device__ __forceinline__ void grid_sync() {
    __syncthreads();
    __threadfence();
    if (threadIdx.x == 0) {
        unsigned gen = *((volatile unsigned*)&d_bar_gen);
        unsigned t = atomicAdd(&d_bar_count, 1u);
        if (t == NB - 1) {
            d_bar_count = 0;
            __threadfence();
            atomicAdd(&d_bar_gen, 1u);
        } else {
            while (*((volatile unsigned*)&d_bar_gen) == gen) { __nanosleep(64); }
        }
    }
    __threadfence();
    __syncthreads();
}

__device__ __forceinline__ unsigned long long warp_min_u64(unsigned long long v) {
#pragma unroll
    for (int s = 16; s > 0; s >>= 1) {
        unsigned long long o = __shfl_xor_sync(0xffffffffu, v, s);
        v = o < v ? o : v;
    }
    return v;
}
__device__ __forceinline__ unsigned long long u64min(unsigned long long a, unsigned long long b) {
    return a < b ? a : b;
}
__device__ __forceinline__ unsigned long long u64max(unsigned long long a, unsigned long long b) {
    return a > b ? a : b;
}

__global__ __launch_bounds__(NT, 3)
void fused_kernel(const float* __restrict__ preds,
                  const float* __restrict__ gt_boxes,
                  const int* __restrict__ gt_classes,
                  const int* __restrict__ epoch_p,
                  const int* __restrict__ tot_p,
                  float* __restrict__ out,
                  int NP, int NG) {
    __shared__ float s_tile[64][NCC + 1];               // 20.7 KB (stage A)
    __shared__ float sgx1[GCH], sgy1[GCH], sgx2[GCH], sgy2[GCH];
    __shared__ float sgar[GCH], sgat[GCH], sgcx[GCH], sgcy[GCH];
    __shared__ int   scls[GCH];
    __shared__ float2* sout[GCH];
    __shared__ int s_hist[NCC + 1];
    __shared__ unsigned s_u;
    __shared__ unsigned long long s_warp[NT / 32];
    __shared__ unsigned long long s_win;

    int tid = threadIdx.x;
    int bid = blockIdx.x;
    int lane = tid & 31, wid = tid >> 5;
    int n4 = NP >> 2;
    int n2 = NP >> 1;
    float* cost = out;

    // ================= stage A: prep + class-sort =================
    if (bid == 0) {
        for (int g = tid; g < NG; g += NT) {
            float x1 = gt_boxes[g * 4 + 0], y1 = gt_boxes[g * 4 + 1];
            float x2 = gt_boxes[g * 4 + 2], y2 = gt_boxes[g * 4 + 3];
            d_gx1[g] = x1; d_gy1[g] = y1; d_gx2[g] = x2; d_gy2[g] = y2;
            d_garea[g] = fmaxf(x2 - x1, 0.f) * fmaxf(y2 - y1, 0.f);
            float wg = fmaxf(x2 - x1, EPSF), hg = fmaxf(y2 - y1, EPSF);
            d_gatan[g] = atanf(wg / hg);
            d_gcx[g] = 0.5f * (x1 + x2);
            d_gcy[g] = 0.5f * (y1 + y2);
            d_gcls[g] = gt_classes[g];
        }
        if (tid == 0) { d_unit_ctr = 0; d_row_ctr = 0; }
        // counting sort of gts by class (order within class irrelevant)
        if (tid <= NCC) s_hist[tid] = 0;
        __syncthreads();
        if (tid < NG) atomicAdd(&s_hist[gt_classes[tid]], 1);
        __syncthreads();
        if (tid == 0) {
            int acc = 0;
            for (int c = 0; c <= NCC; ++c) { int h = s_hist[c]; s_hist[c] = acc; acc += h; }
        }
        __syncthreads();
        if (tid < NG) {
            int pos = atomicAdd(&s_hist[gt_classes[tid]], 1);
            d_sorder[pos] = tid;
        }
    }

    int ntiles = (NP + 63) >> 6;
    for (int tile = bid; tile < ntiles; tile += NB) {
        int p0 = tile << 6;
        int nblk = min(64, NP - p0);
        __syncthreads();   // protect s_tile reuse
        for (int i = tid; i < 64 * NCC; i += NT) {
            int pp = i / NCC, cc = i - pp * NCC;
            float v = 0.f;
            if (pp < nblk) v = preds[(size_t)(p0 + pp) * (5 + NCC) + 5 + cc];
            s_tile[pp][cc] = 1.0f / (1.0f + __expf(-v));
        }
        if (tid < nblk) {
            int p = p0 + tid;
            const float* r = preds + (size_t)p * (5 + NCC);
            float xc = r[0], yc = r[1], w = r[2], h = r[3];
            float x1 = xc - 0.5f * w, y1 = yc - 0.5f * h;
            float x2 = xc + 0.5f * w, y2 = yc + 0.5f * h;
            d_px1[p] = x1; d_py1[p] = y1; d_px2[p] = x2; d_py2[p] = y2;
            d_parea[p] = fmaxf(x2 - x1, 0.f) * fmaxf(y2 - y1, 0.f);
            float wp = fmaxf(x2 - x1, EPSF), hp = fmaxf(y2 - y1, EPSF);
            d_patan[p] = atanf(wp / hp);
            d_pcx[p] = 0.5f * (x1 + x2);
            d_pcy[p] = 0.5f * (y1 + y2);
        }
        __syncthreads();
        for (int i = tid; i < NCC * 64; i += NT) {
            int cc = i >> 6, pp = i & 63;
            if (pp < nblk)
                d_probT[(size_t)cc * NP + p0 + pp] = s_tile[pp][cc];
        }
    }

    grid_sync();

    // ====== stage B: cost matrix (class-sorted g, float2/thread, 1-rcp) =======
    int nq = (n2 + NT - 1) / NT;
    int ngc = (NG + GCH - 1) / GCH;
    unsigned nunits = (unsigned)(nq * ngc);
    for (;;) {
        __syncthreads();   // protect sg*/s_u reuse
        if (tid == 0) s_u = atomicAdd(&d_unit_ctr, 1u);
        __syncthreads();
        unsigned u = s_u;
        if (u >= nunits) break;
        int qc = (int)(u % (unsigned)nq);
        int gc = (int)(u / (unsigned)nq);
        int g0 = gc * GCH;
        int gn = min(GCH, NG - g0);
        if (tid < gn) {
            int gg = d_sorder[g0 + tid];
            sgx1[tid] = d_gx1[gg]; sgy1[tid] = d_gy1[gg];
            sgx2[tid] = d_gx2[gg]; sgy2[tid] = d_gy2[gg];
            sgar[tid] = d_garea[gg]; sgat[tid] = d_gatan[gg];
            sgcx[tid] = d_gcx[gg]; sgcy[tid] = d_gcy[gg];
            scls[tid] = d_gcls[gg];
            sout[tid] = (float2*)(cost + (size_t)gg * NP);
        }
        __syncthreads();

        int q = qc * NT + tid;
        if (q < n2) {
            float2 px1 = ((const float2*)d_px1)[q], py1 = ((const float2*)d_py1)[q];
            float2 px2 = ((const float2*)d_px2)[q], py2 = ((const float2*)d_py2)[q];
            float2 par = ((const float2*)d_parea)[q], pat = ((const float2*)d_patan)[q];
            float2 pcx = ((const float2*)d_pcx)[q], pcy = ((const float2*)d_pcy)[q];
            int prevc = -1;
            float2 cp = make_float2(0.f, 0.f);
            for (int s = 0; s < gn; ++s) {
                int c = scls[s];                    // uniform across block
                if (c != prevc) {                   // ~5 loads per 16 sorted g's
                    cp = ((const float2*)(d_probT + (size_t)c * NP))[q];
                    prevc = c;
                }
                float gx1 = sgx1[s], gy1 = sgy1[s], gx2 = sgx2[s], gy2 = sgy2[s];
                float gar = sgar[s], gat = sgat[s], gcx = sgcx[s], gcy = sgcy[s];
                float2 o;
                const float* PX1 = &px1.x; const float* PY1 = &py1.x;
                const float* PX2 = &px2.x; const float* PY2 = &py2.x;
                const float* PAR = &par.x; const float* PAT = &pat.x;
                const float* PCX = &pcx.x; const float* PCY = &pcy.x;
                const float* CP = &cp.x; float* OUT = &o.x;
#pragma unroll
                for (int j = 0; j < 2; ++j) {
                    float ix1 = fmaxf(PX1[j], gx1), iy1 = fmaxf(PY1[j], gy1);
                    float ix2 = fminf(PX2[j], gx2), iy2 = fminf(PY2[j], gy2);
                    float inter = fmaxf(ix2 - ix1, 0.f) * fmaxf(iy2 - iy1, 0.f);
                    float uni = PAR[j] + gar - inter + EPSF;
                    float dx = PCX[j] - gcx, dy = PCY[j] - gcy;
                    float d2 = dx * dx + dy * dy;
                    float cw = fmaxf(fmaxf(PX2[j], gx2) - fminf(PX1[j], gx1), EPSF);
                    float ch = fmaxf(fmaxf(PY2[j], gy2) - fminf(PY1[j], gy1), EPSF);
                    float c2 = cw * cw + ch * ch + EPSF;
                    float dat = gat - PAT[j];
                    float v = C_V * dat * dat;
                    // --- single-reciprocal CIoU ---
                    // D = uni*(1 - iou + v + EPS) = uni*(1 + v + EPS) - inter
                    float D  = uni * (1.0f + v + EPSF) - inter;
                    float t1 = c2 * D;           // iou   = inter * t1 * r
                    float t2 = uni * D;          // d2/c2 = d2    * t2 * r
                    float t3 = uni * c2;         // 1/D   =         t3 * r
                    float r  = __fdividef(1.0f, t3 * D);
                    float iou  = inter * t1 * r;
                    float ciou = iou - d2 * t2 * r - (v * v * uni) * (t3 * r);
                    OUT[j] = 0.75f * (1.0f - CP[j]) + (1.0f - fminf(fmaxf(ciou, 0.f), 1.f));
                }
                sout[s][q] = o;
            }
        }
    }

    grid_sync();

    // ================= stage C: per-row exact top-K (single wave) =============
    int ep = epoch_p[0];
    int te = tot_p[0];
    float tt = (float)ep / (float)max(1, te - 1);
    int K = (int)rintf(10.0f - 9.0f * tt);
    K = min(10, max(1, K));
    K = min(K, NP);

    const float INF = __int_as_float(0x7f800000);

    for (;;) {
        __syncthreads();   // protect s_u / s_warp reuse
        if (tid == 0) s_u = atomicAdd(&d_row_ctr, 1u);
        __syncthreads();
        unsigned g = s_u;
        if (g >= (unsigned)NG) break;

        const float4* row4 = (const float4*)(cost + (size_t)g * NP);

        // guarded float-compare top-2 scan (all costs > 0; increasing p per
        // thread, strict < => earliest index wins ties, matching jax order)
        float f1 = INF, f2 = INF;
        int i1 = 0, i2 = -1;
        for (int i = tid; i < n4; i += NT) {
            float4 v = row4[i];
            int p = i << 2;
            if (v.x < f2) {
                if (v.x < f1) { f2 = f1; i2 = i1; f1 = v.x; i1 = p; }
                else          { f2 = v.x; i2 = p; }
            }
            if (v.y < f2) {
                if (v.y < f1) { f2 = f1; i2 = i1; f1 = v.y; i1 = p + 1; }
                else          { f2 = v.y; i2 = p + 1; }
            }
            if (v.z < f2) {
                if (v.z < f1) { f2 = f1; i2 = i1; f1 = v.z; i1 = p + 2; }
                else          { f2 = v.z; i2 = p + 2; }
            }
            if (v.w < f2) {
                if (v.w < f1) { f2 = f1; i2 = i1; f1 = v.w; i1 = p + 3; }
                else          { f2 = v.w; i2 = p + 3; }
            }
        }
        for (int p = (n4 << 2) + tid; p < NP; p += NT) {
            float v = cost[(size_t)g * NP + p];
            if (v < f2) {
                if (v < f1) { f2 = f1; i2 = i1; f1 = v; i1 = p; }
                else        { f2 = v; i2 = p; }
            }
        }
        // pack into u64 keys (positive floats: bit order == numeric order)
        unsigned long long m1 = (f1 == INF) ? ~0ULL
            : (((unsigned long long)__float_as_uint(f1) << 32) | (unsigned)i1);
        unsigned long long m2 = (i2 < 0) ? ~0ULL
            : (((unsigned long long)__float_as_uint(f2) << 32) | (unsigned)i2);

        for (int r = 0; r < K; ++r) {
            unsigned long long w = warp_min_u64(m1);
            if (lane == 0) s_warp[wid] = w;
            __syncthreads();
            if (wid == 0) {
                unsigned long long v = (lane < NT / 32) ? s_warp[lane] : ~0ULL;
                v = warp_min_u64(v);
                if (lane == 0) s_win = v;
            }
            __syncthreads();
            unsigned long long win = s_win;
            if (tid == 0) {
                int p = (int)(unsigned)(win & 0xffffffffULL);
                size_t base = (size_t)NG * NP + 2 * ((size_t)g * K + r);
                out[base + 0] = (float)p;
                out[base + 1] = (float)g;
            }
            if (m1 == win) {
                if (m2 != ~0ULL) { m1 = m2; m2 = ~0ULL; }
                else {
                    // rare: this thread won twice -> exact u64 rescan for keys > win
                    unsigned long long a1 = ~0ULL, a2 = ~0ULL;
                    for (int i = tid; i < n4; i += NT) {
                        float4 v = row4[i];
                        int p = i << 2;
                        unsigned long long kk[4];
                        kk[0] = ((unsigned long long)__float_as_uint(v.x) << 32) | (unsigned)(p);
                        kk[1] = ((unsigned long long)__float_as_uint(v.y) << 32) | (unsigned)(p + 1);
                        kk[2] = ((unsigned long long)__float_as_uint(v.z) << 32) | (unsigned)(p + 2);
                        kk[3] = ((unsigned long long)__float_as_uint(v.w) << 32) | (unsigned)(p + 3);
#pragma unroll
                        for (int j = 0; j < 4; ++j) {
                            unsigned long long k = kk[j];
                            if (k > win) { a2 = u64min(a2, u64max(a1, k)); a1 = u64min(a1, k); }
                        }
                    }
                    for (int p = (n4 << 2) + tid; p < NP; p += NT) {
                        unsigned long long k =
                            ((unsigned long long)__float_as_uint(cost[(size_t)g * NP + p]) << 32) | (unsigned)p;
                        if (k > win) { a2 = u64min(a2, u64max(a1, k)); a1 = u64min(a1, k); }
                    }
                    m1 = a1; m2 = a2;
                }
            }
            __syncthreads();
        }
    }
}

extern "C" void kernel_launch(void* const* d_in, const int* in_sizes, int n_in,
                              void* d_out, int out_size) {
    const float* preds      = (const float*)d_in[0];
    const float* gt_boxes   = (const float*)d_in[1];
    const int*   gt_classes = (const int*)d_in[2];
    const int*   epoch      = (const int*)d_in[3];
    const int*   tot        = (const int*)d_in[4];

    int NP = in_sizes[0] / (5 + NCC);
    int NG = in_sizes[2];
    float* out = (float*)d_out;

    fused_kernel<<<NB, NT>>>(preds, gt_boxes, gt_classes, epoch, tot, out, NP, NG);
}

// round 17
// speedup vs baseline: 1.0932x; 1.0932x over previous
#include <cuda_runtime.h>
#include <cstdint>

#define NCC   80
#define NGMAX 300
#define NPMAX 100000
#define EPSF  1e-7f
#define C_V   0.4052847345693511f   // 4/pi^2
#define NB    444                   // 3 blocks/SM on 148 SMs (co-resident on 152 too)
#define NT    512                   // 16 warps/block -> 48 warps/SM
#define GCH   16                    // sorted g-rows per cost unit

// ---- scratch (static device arrays; 16B-aligned for vector access) ----
__device__ __align__(16) float d_probT[(size_t)NCC * NPMAX];   // [class][pred]
__device__ __align__(16) float d_px1[NPMAX], d_py1[NPMAX], d_px2[NPMAX], d_py2[NPMAX];
__device__ __align__(16) float d_parea[NPMAX], d_patan[NPMAX], d_pcx[NPMAX], d_pcy[NPMAX];
__device__ float d_gx1[NGMAX], d_gy1[NGMAX], d_gx2[NGMAX], d_gy2[NGMAX];
__device__ float d_garea[NGMAX], d_gatan[NGMAX], d_gcx[NGMAX], d_gcy[NGMAX];
__device__ int   d_gcls[NGMAX];
__device__ int   d_sorder[NGMAX];   // gt indices sorted by class

// barrier + work counters
__device__ unsigned d_bar_count = 0;
__device__ unsigned d_bar_gen   = 0;
__device__ unsigned d_unit_ctr  = 0;
__device__ unsigned d_row_ctr   = 0;

__device__ __forceinline__ void grid_sync() {
    __syncthreads();
    __threadfence();
    if (threadIdx.x == 0) {
        unsigned gen = *((volatile unsigned*)&d_bar_gen);
        unsigned t = atomicAdd(&d_bar_count, 1u);
        if (t == NB - 1) {
            d_bar_count = 0;
            __threadfence();
            atomicAdd(&d_bar_gen, 1u);
        } else {
            while (*((volatile unsigned*)&d_bar_gen) == gen) { __nanosleep(64); }
        }
    }
    __threadfence();
    __syncthreads();
}

__device__ __forceinline__ unsigned long long warp_min_u64(unsigned long long v) {
#pragma unroll
    for (int s = 16; s > 0; s >>= 1) {
        unsigned long long o = __shfl_xor_sync(0xffffffffu, v, s);
        v = o < v ? o : v;
    }
    return v;
}
__device__ __forceinline__ unsigned long long u64min(unsigned long long a, unsigned long long b) {
    return a < b ? a : b;
}
__device__ __forceinline__ unsigned long long u64max(unsigned long long a, unsigned long long b) {
    return a > b ? a : b;
}

__global__ __launch_bounds__(NT, 3)
void fused_kernel(const float* __restrict__ preds,
                  const float* __restrict__ gt_boxes,
                  const int* __restrict__ gt_classes,
                  const int* __restrict__ epoch_p,
                  const int* __restrict__ tot_p,
                  float* __restrict__ out,
                  int NP, int NG) {
    __shared__ float s_tile[64][NCC + 1];               // 20.7 KB (stage A)
    __shared__ float4 sgb[GCH];    // {x1,y1,x2,y2}
    __shared__ float4 sgm[GCH];    // {area, atan, cx, cy}
    __shared__ int    scls[GCH];
    __shared__ float2* sout[GCH];
    __shared__ int s_hist[NCC + 1];
    __shared__ unsigned s_u;
    __shared__ unsigned long long s_warp[NT / 32];
    __shared__ unsigned long long s_win;

    int tid = threadIdx.x;
    int bid = blockIdx.x;
    int lane = tid & 31, wid = tid >> 5;
    int n4 = NP >> 2;
    int n2 = NP >> 1;
    float* cost = out;

    // ================= stage A: prep + class-sort =================
    if (bid == 0) {
        for (int g = tid; g < NG; g += NT) {
            float x1 = gt_boxes[g * 4 + 0], y1 = gt_boxes[g * 4 + 1];
            float x2 = gt_boxes[g * 4 + 2], y2 = gt_boxes[g * 4 + 3];
            d_gx1[g] = x1; d_gy1[g] = y1; d_gx2[g] = x2; d_gy2[g] = y2;
            d_garea[g] = fmaxf(x2 - x1, 0.f) * fmaxf(y2 - y1, 0.f);
            float wg = fmaxf(x2 - x1, EPSF), hg = fmaxf(y2 - y1, EPSF);
            d_gatan[g] = atanf(wg / hg);
            d_gcx[g] = 0.5f * (x1 + x2);
            d_gcy[g] = 0.5f * (y1 + y2);
            d_gcls[g] = gt_classes[g];
        }
        if (tid == 0) { d_unit_ctr = 0; d_row_ctr = 0; }
        // counting sort of gts by class (order within class irrelevant)
        if (tid <= NCC) s_hist[tid] = 0;
        __syncthreads();
        if (tid < NG) atomicAdd(&s_hist[gt_classes[tid]], 1);
        __syncthreads();
        if (tid == 0) {
            int acc = 0;
            for (int c = 0; c <= NCC; ++c) { int h = s_hist[c]; s_hist[c] = acc; acc += h; }
        }
        __syncthreads();
        if (tid < NG) {
            int pos = atomicAdd(&s_hist[gt_classes[tid]], 1);
            d_sorder[pos] = tid;
        }
    }

    int ntiles = (NP + 63) >> 6;
    for (int tile = bid; tile < ntiles; tile += NB) {
        int p0 = tile << 6;
        int nblk = min(64, NP - p0);
        __syncthreads();   // protect s_tile reuse
        for (int i = tid; i < 64 * NCC; i += NT) {
            int pp = i / NCC, cc = i - pp * NCC;
            float v = 0.f;
            if (pp < nblk) v = preds[(size_t)(p0 + pp) * (5 + NCC) + 5 + cc];
            s_tile[pp][cc] = 1.0f / (1.0f + __expf(-v));
        }
        if (tid < nblk) {
            int p = p0 + tid;
            const float* r = preds + (size_t)p * (5 + NCC);
            float xc = r[0], yc = r[1], w = r[2], h = r[3];
            float x1 = xc - 0.5f * w, y1 = yc - 0.5f * h;
            float x2 = xc + 0.5f * w, y2 = yc + 0.5f * h;
            d_px1[p] = x1; d_py1[p] = y1; d_px2[p] = x2; d_py2[p] = y2;
            d_parea[p] = fmaxf(x2 - x1, 0.f) * fmaxf(y2 - y1, 0.f);
            float wp = fmaxf(x2 - x1, EPSF), hp = fmaxf(y2 - y1, EPSF);
            d_patan[p] = atanf(wp / hp);
            d_pcx[p] = 0.5f * (x1 + x2);
            d_pcy[p] = 0.5f * (y1 + y2);
        }
        __syncthreads();
        for (int i = tid; i < NCC * 64; i += NT) {
            int cc = i >> 6, pp = i & 63;
            if (pp < nblk)
                d_probT[(size_t)cc * NP + p0 + pp] = s_tile[pp][cc];
        }
    }

    grid_sync();

    // ====== stage B: cost (class-sorted g, float2/thread, packed GT smem) =====
    int nq = (n2 + NT - 1) / NT;
    int ngc = (NG + GCH - 1) / GCH;
    unsigned nunits = (unsigned)(nq * ngc);
    for (;;) {
        __syncthreads();   // protect sg*/s_u reuse
        if (tid == 0) s_u = atomicAdd(&d_unit_ctr, 1u);
        __syncthreads();
        unsigned u = s_u;
        if (u >= nunits) break;
        int qc = (int)(u % (unsigned)nq);
        int gc = (int)(u / (unsigned)nq);
        int g0 = gc * GCH;
        int gn = min(GCH, NG - g0);
        if (tid < gn) {
            int gg = d_sorder[g0 + tid];
            sgb[tid] = make_float4(d_gx1[gg], d_gy1[gg], d_gx2[gg], d_gy2[gg]);
            sgm[tid] = make_float4(d_garea[gg], d_gatan[gg], d_gcx[gg], d_gcy[gg]);
            scls[tid] = d_gcls[gg];
            sout[tid] = (float2*)(cost + (size_t)gg * NP);
        }
        __syncthreads();

        int q = qc * NT + tid;
        if (q < n2) {
            float2 px1 = ((const float2*)d_px1)[q], py1 = ((const float2*)d_py1)[q];
            float2 px2 = ((const float2*)d_px2)[q], py2 = ((const float2*)d_py2)[q];
            float2 par = ((const float2*)d_parea)[q], pat = ((const float2*)d_patan)[q];
            float2 pcx = ((const float2*)d_pcx)[q], pcy = ((const float2*)d_pcy)[q];
            int prevc = -1;
            float2 cp = make_float2(0.f, 0.f);
            for (int s = 0; s < gn; ++s) {
                int c = scls[s];                    // uniform across block
                if (c != prevc) {                   // ~5 loads per 16 sorted g's
                    cp = ((const float2*)(d_probT + (size_t)c * NP))[q];
                    prevc = c;
                }
                float4 gb = sgb[s], gm = sgm[s];    // 2x LDS.128
                float gx1 = gb.x, gy1 = gb.y, gx2 = gb.z, gy2 = gb.w;
                float gar = gm.x, gat = gm.y, gcx = gm.z, gcy = gm.w;
                float2 o;
                const float* PX1 = &px1.x; const float* PY1 = &py1.x;
                const float* PX2 = &px2.x; const float* PY2 = &py2.x;
                const float* PAR = &par.x; const float* PAT = &pat.x;
                const float* PCX = &pcx.x; const float* PCY = &pcy.x;
                const float* CP = &cp.x; float* OUT = &o.x;
#pragma unroll
                for (int j = 0; j < 2; ++j) {
                    float ix1 = fmaxf(PX1[j], gx1), iy1 = fmaxf(PY1[j], gy1);
                    float ix2 = fminf(PX2[j], gx2), iy2 = fminf(PY2[j], gy2);
                    float inter = fmaxf(ix2 - ix1, 0.f) * fmaxf(iy2 - iy1, 0.f);
                    float uni = PAR[j] + gar - inter + EPSF;
                    float dx = PCX[j] - gcx, dy = PCY[j] - gcy;
                    float d2 = dx * dx + dy * dy;
                    float cw = fmaxf(fmaxf(PX2[j], gx2) - fminf(PX1[j], gx1), EPSF);
                    float ch = fmaxf(fmaxf(PY2[j], gy2) - fminf(PY1[j], gy1), EPSF);
                    float c2 = cw * cw + ch * ch + EPSF;
                    float dat = gat - PAT[j];
                    float v = C_V * dat * dat;
                    // --- single-reciprocal CIoU ---
                    float D  = uni * (1.0f + v + EPSF) - inter;
                    float t1 = c2 * D;
                    float t2 = uni * D;
                    float t3 = uni * c2;
                    float r  = __fdividef(1.0f, t3 * D);
                    float iou  = inter * t1 * r;
                    float ciou = iou - d2 * t2 * r - (v * v * uni) * (t3 * r);
                    OUT[j] = 0.75f * (1.0f - CP[j]) + (1.0f - fminf(fmaxf(ciou, 0.f), 1.f));
                }
                sout[s][q] = o;
            }
        }
    }

    grid_sync();

    // ======== stage C: per-row exact top-K (fmin-tree fast-path scan) =========
    int ep = epoch_p[0];
    int te = tot_p[0];
    float tt = (float)ep / (float)max(1, te - 1);
    int K = (int)rintf(10.0f - 9.0f * tt);
    K = min(10, max(1, K));
    K = min(K, NP);

    const float INF = __int_as_float(0x7f800000);

    for (;;) {
        __syncthreads();   // protect s_u / s_warp reuse
        if (tid == 0) s_u = atomicAdd(&d_row_ctr, 1u);
        __syncthreads();
        unsigned g = s_u;
        if (g >= (unsigned)NG) break;

        const float4* row4 = (const float4*)(cost + (size_t)g * NP);

        // fast path: 4-wide fmin tree; slow path (rare) replays the exact
        // increasing-p ordered top-2 update -> identical results + tie-break.
        float f1 = INF, f2 = INF;
        int i1 = 0, i2 = -1;
        for (int i = tid; i < n4; i += NT) {
            float4 v = row4[i];
            float m = fminf(fminf(v.x, v.y), fminf(v.z, v.w));
            if (m < f2) {
                int p = i << 2;
                if (v.x < f2) {
                    if (v.x < f1) { f2 = f1; i2 = i1; f1 = v.x; i1 = p; }
                    else          { f2 = v.x; i2 = p; }
                }
                if (v.y < f2) {
                    if (v.y < f1) { f2 = f1; i2 = i1; f1 = v.y; i1 = p + 1; }
                    else          { f2 = v.y; i2 = p + 1; }
                }
                if (v.z < f2) {
                    if (v.z < f1) { f2 = f1; i2 = i1; f1 = v.z; i1 = p + 2; }
                    else          { f2 = v.z; i2 = p + 2; }
                }
                if (v.w < f2) {
                    if (v.w < f1) { f2 = f1; i2 = i1; f1 = v.w; i1 = p + 3; }
                    else          { f2 = v.w; i2 = p + 3; }
                }
            }
        }
        for (int p = (n4 << 2) + tid; p < NP; p += NT) {
            float v = cost[(size_t)g * NP + p];
            if (v < f2) {
                if (v < f1) { f2 = f1; i2 = i1; f1 = v; i1 = p; }
                else        { f2 = v; i2 = p; }
            }
        }
        // pack into u64 keys (positive floats: bit order == numeric order)
        unsigned long long m1 = (f1 == INF) ? ~0ULL
            : (((unsigned long long)__float_as_uint(f1) << 32) | (unsigned)i1);
        unsigned long long m2 = (i2 < 0) ? ~0ULL
            : (((unsigned long long)__float_as_uint(f2) << 32) | (unsigned)i2);

        for (int r = 0; r < K; ++r) {
            unsigned long long w = warp_min_u64(m1);
            if (lane == 0) s_warp[wid] = w;
            __syncthreads();
            if (wid == 0) {
                unsigned long long v = (lane < NT / 32) ? s_warp[lane] : ~0ULL;
                v = warp_min_u64(v);
                if (lane == 0) s_win = v;
            }
            __syncthreads();
            unsigned long long win = s_win;
            if (tid == 0) {
                int p = (int)(unsigned)(win & 0xffffffffULL);
                size_t base = (size_t)NG * NP + 2 * ((size_t)g * K + r);
                out[base + 0] = (float)p;
                out[base + 1] = (float)g;
            }
            if (m1 == win) {
                if (m2 != ~0ULL) { m1 = m2; m2 = ~0ULL; }
                else {
                    // rare: this thread won twice -> exact u64 rescan for keys > win
                    unsigned long long a1 = ~0ULL, a2 = ~0ULL;
                    for (int i = tid; i < n4; i += NT) {
                        float4 v = row4[i];
                        int p = i << 2;
                        unsigned long long kk[4];
                        kk[0] = ((unsigned long long)__float_as_uint(v.x) << 32) | (unsigned)(p);
                        kk[1] = ((unsigned long long)__float_as_uint(v.y) << 32) | (unsigned)(p + 1);
                        kk[2] = ((unsigned long long)__float_as_uint(v.z) << 32) | (unsigned)(p + 2);
                        kk[3] = ((unsigned long long)__float_as_uint(v.w) << 32) | (unsigned)(p + 3);
#pragma unroll
                        for (int j = 0; j < 4; ++j) {
                            unsigned long long k = kk[j];
                            if (k > win) { a2 = u64min(a2, u64max(a1, k)); a1 = u64min(a1, k); }
                        }
                    }
                    for (int p = (n4 << 2) + tid; p < NP; p += NT) {
                        unsigned long long k =
                            ((unsigned long long)__float_as_uint(cost[(size_t)g * NP + p]) << 32) | (unsigned)p;
                        if (k > win) { a2 = u64min(a2, u64max(a1, k)); a1 = u64min(a1, k); }
                    }
                    m1 = a1; m2 = a2;
                }
            }
            __syncthreads();
        }
    }
}

extern "C" void kernel_launch(void* const* d_in, const int* in_sizes, int n_in,
                              void* d_out, int out_size) {
    const float* preds      = (const float*)d_in[0];
    const float* gt_boxes   = (const float*)d_in[1];
    const int*   gt_classes = (const int*)d_in[2];
    const int*   epoch      = (const int*)d_in[3];
    const int*   tot        = (const int*)d_in[4];

    int NP = in_sizes[0] / (5 + NCC);
    int NG = in_sizes[2];
    float* out = (float*)d_out;

    fused_kernel<<<NB, NT>>>(preds, gt_boxes, gt_classes, epoch, tot, out, NP, NG);
}